// round 2
// baseline (speedup 1.0000x reference)
#include <cuda_runtime.h>

// out[b,i,d] = x[b,i] * W[i,d] + b[i,d]
// B=128, N=1024, D=512 (fp32). DRAM-write-bound: 268MB out, 4.5MB in.
// Strategy: register-cache W/b per thread, iterate batch chunk -> no
// per-output L2 re-reads of W/b.

#define BB 128
#define NN 1024
#define DD 512
#define D4 (DD / 4)          // 128 float4 per row
#define B_PER_BLOCK 16       // batch chunk per block

__global__ __launch_bounds__(D4, 8)
void fused_scalar_linear_kernel(const float* __restrict__ x,
                                const float4* __restrict__ W,
                                const float4* __restrict__ bias,
                                float4* __restrict__ out) {
    const int i  = blockIdx.x;       // neuron row 0..NN-1
    const int bc = blockIdx.y;       // batch chunk 0..BB/B_PER_BLOCK-1
    const int d4 = threadIdx.x;      // 0..D4-1

    // One-time register load of this thread's W/b slice (L2/DRAM read once).
    const float4 w  = W[i * D4 + d4];
    const float4 bv = bias[i * D4 + d4];

    const int b0 = bc * B_PER_BLOCK;

    // Prefetch all x scalars for the chunk up front (independent LDGs -> MLP).
    float xs[B_PER_BLOCK];
    #pragma unroll
    for (int k = 0; k < B_PER_BLOCK; ++k) {
        xs[k] = __ldg(&x[(size_t)(b0 + k) * NN + i]);
    }

    #pragma unroll
    for (int k = 0; k < B_PER_BLOCK; ++k) {
        float4 o;
        o.x = fmaf(xs[k], w.x, bv.x);
        o.y = fmaf(xs[k], w.y, bv.y);
        o.z = fmaf(xs[k], w.z, bv.z);
        o.w = fmaf(xs[k], w.w, bv.w);
        // Row store: 128 threads x 16B = 2KB contiguous, fully coalesced.
        out[(size_t)(b0 + k) * NN * D4 + (size_t)i * D4 + d4] = o;
    }
}

extern "C" void kernel_launch(void* const* d_in, const int* in_sizes, int n_in,
                              void* d_out, int out_size) {
    const float*  x    = (const float*)d_in[0];   // [B, N, 1]
    const float4* W    = (const float4*)d_in[1];  // [N, D]
    const float4* bias = (const float4*)d_in[2];  // [N, D]
    float4* out = (float4*)d_out;                 // [B, N, D]

    dim3 grid(NN, BB / B_PER_BLOCK);
    fused_scalar_linear_kernel<<<grid, D4>>>(x, W, bias, out);
}